// round 4
// baseline (speedup 1.0000x reference)
#include <cuda_runtime.h>

#define N_NODES   100000
#define N_EDGES   600000
#define D_FEAT    128
#define N_CLASSES 40

// Scratch (allocation-free rule: __device__ globals)
__device__ float g_bufA[(size_t)N_NODES * D_FEAT];  // message source u
__device__ float g_bufB[(size_t)N_NODES * D_FEAT];  // accumulator
__device__ int   g_deg[N_NODES];
__device__ float g_dinv[N_NODES];
__device__ int   g_src[N_EDGES];
__device__ int   g_dst[N_EDGES];
__device__ unsigned g_fmt;   // 0 -> edge_index is int64, nonzero -> int32

// ---- dtype probe: OR all odd int32 words of the first 1.2M words ----------
// int64 encoding (values < 1e5): odd words are high halves == 0  -> OR == 0
// int32 encoding: odd words are random node ids                  -> OR != 0
__global__ void k_init_probe(const int* __restrict__ e32) {
    int i = blockIdx.x * blockDim.x + threadIdx.x;
    if (i == 0) g_fmt = 0u;               // benign race: decode runs next launch
    if (i < N_NODES) g_deg[i] = 0;
}

__global__ void k_probe(const int* __restrict__ e32) {
    int i = blockIdx.x * blockDim.x + threadIdx.x;
    unsigned v = 0;
    if (i < N_EDGES) v = (unsigned)e32[2 * i + 1];
    // warp-reduce the OR to keep same-address atomics rare
    #pragma unroll
    for (int off = 16; off; off >>= 1)
        v |= __shfl_xor_sync(0xffffffffu, v, off);
    if ((threadIdx.x & 31) == 0 && v) atomicOr(&g_fmt, v);
}

// ---- decode edges into int32 src/dst (clamped), count in-degree -----------
__global__ void k_decode_count(const int* __restrict__ e32) {
    int e = blockIdx.x * blockDim.x + threadIdx.x;
    if (e >= N_EDGES) return;
    int s, d;
    if (g_fmt) {                      // int32: row0 = src, row1 = dst
        s = e32[e];
        d = e32[N_EDGES + e];
    } else {                          // int64: take low words
        s = e32[2 * e];
        d = e32[2 * (N_EDGES + e)];
    }
    if ((unsigned)s >= N_NODES) s = 0;   // defensive: fail soft, not err 717
    if ((unsigned)d >= N_NODES) d = 0;
    g_src[e] = s;
    g_dst[e] = d;
    atomicAdd(&g_deg[d], 1);
}

__global__ void k_dinv() {
    int i = blockIdx.x * blockDim.x + threadIdx.x;
    if (i < N_NODES) g_dinv[i] = rsqrtf((float)g_deg[i] + 1.0f);
}

// u = dinv * x ; bufA = u (messages), bufB = u (self-loop init of accumulator)
__global__ void k_scale_init(const float4* __restrict__ x) {
    int t = blockIdx.x * blockDim.x + threadIdx.x;      // one float4 per thread
    if (t >= N_NODES * (D_FEAT / 4)) return;
    int node = t >> 5;                                   // 32 float4 per row
    float d = g_dinv[node];
    float4 v = x[t];
    v.x *= d; v.y *= d; v.z *= d; v.w *= d;
    ((float4*)g_bufA)[t] = v;
    ((float4*)g_bufB)[t] = v;
}

// between rounds: u2 = dinv^2 * acc1 ; bufA = u2, bufB = u2
__global__ void k_rescale() {
    int t = blockIdx.x * blockDim.x + threadIdx.x;
    if (t >= N_NODES * (D_FEAT / 4)) return;
    int node = t >> 5;
    float d = g_dinv[node]; d = d * d;
    float4 v = ((const float4*)g_bufB)[t];
    v.x *= d; v.y *= d; v.z *= d; v.w *= d;
    ((float4*)g_bufA)[t] = v;
    ((float4*)g_bufB)[t] = v;
}

// one warp per edge; lane handles features {lane, lane+32, lane+64, lane+96}
// -> every load / atomicAdd instruction is a fully coalesced 128B transaction
__global__ void k_scatter() {
    int w    = (blockIdx.x * blockDim.x + threadIdx.x) >> 5;
    int lane = threadIdx.x & 31;
    if (w >= N_EDGES) return;
    int s = g_src[w];
    int d = g_dst[w];
    const float* __restrict__ srow = g_bufA + (size_t)s * D_FEAT;
    float* drow = g_bufB + (size_t)d * D_FEAT;
    float v0 = srow[lane];
    float v1 = srow[lane + 32];
    float v2 = srow[lane + 64];
    float v3 = srow[lane + 96];
    atomicAdd(drow + lane,      v0);
    atomicAdd(drow + lane + 32, v1);
    atomicAdd(drow + lane + 64, v2);
    atomicAdd(drow + lane + 96, v3);
}

// classifier: x_final = dinv * bufB ; logits = x_final @ W^T + b ; log_softmax
// one warp per node; lane owns classes {lane, lane+32}; W staged in shared as
// float2 pairs Wp[k][c] = (W[c][k], W[c+32][k]) -> conflict-free LDS.64
__global__ void k_classify(const float* __restrict__ W,
                           const float* __restrict__ b,
                           float* __restrict__ out) {
    __shared__ float2 Wp[D_FEAT * 32];
    __shared__ float  bsh[64];
    __shared__ float  xsh[8][D_FEAT];

    for (int idx = threadIdx.x; idx < D_FEAT * 32; idx += blockDim.x) {
        int k = idx >> 5, c = idx & 31;
        float w0 = W[c * D_FEAT + k];
        float w1 = (c + 32 < N_CLASSES) ? W[(c + 32) * D_FEAT + k] : 0.0f;
        Wp[idx] = make_float2(w0, w1);
    }
    if (threadIdx.x < 64)
        bsh[threadIdx.x] = (threadIdx.x < N_CLASSES) ? b[threadIdx.x] : 0.0f;
    __syncthreads();

    int lane   = threadIdx.x & 31;
    int wlocal = threadIdx.x >> 5;
    int gwarp  = blockIdx.x * (blockDim.x >> 5) + wlocal;
    int nwarps = gridDim.x * (blockDim.x >> 5);

    for (int node = gwarp; node < N_NODES; node += nwarps) {
        float dv = g_dinv[node];
        float4 xv = ((const float4*)g_bufB)[node * 32 + lane];
        xv.x *= dv; xv.y *= dv; xv.z *= dv; xv.w *= dv;
        ((float4*)xsh[wlocal])[lane] = xv;
        __syncwarp();

        float acc0 = bsh[lane];
        float acc1 = bsh[lane + 32];
        #pragma unroll 8
        for (int k = 0; k < D_FEAT; k++) {
            float xk = xsh[wlocal][k];
            float2 wp = Wp[(k << 5) | lane];
            acc0 = fmaf(xk, wp.x, acc0);
            acc1 = fmaf(xk, wp.y, acc1);
        }

        float v1 = (lane < 8) ? acc1 : -1e30f;
        float m = fmaxf(acc0, v1);
        #pragma unroll
        for (int off = 16; off; off >>= 1)
            m = fmaxf(m, __shfl_xor_sync(0xffffffffu, m, off));
        float s = expf(acc0 - m) + ((lane < 8) ? expf(acc1 - m) : 0.0f);
        #pragma unroll
        for (int off = 16; off; off >>= 1)
            s += __shfl_xor_sync(0xffffffffu, s, off);
        float ls = m + logf(s);

        out[node * N_CLASSES + lane] = acc0 - ls;
        if (lane < 8)
            out[node * N_CLASSES + 32 + lane] = acc1 - ls;
        __syncwarp();
    }
}

extern "C" void kernel_launch(void* const* d_in, const int* in_sizes, int n_in,
                              void* d_out, int out_size) {
    const float* x  = (const float*)d_in[0];
    const int*   ei = (const int*)d_in[1];   // dtype resolved on device (g_fmt)
    const float* W  = (const float*)d_in[2];
    const float* b  = (const float*)d_in[3];
    float* out = (float*)d_out;

    const int T = 256;
    const int nodeBlocks = (N_NODES + T - 1) / T;
    const int edgeBlocks = (N_EDGES + T - 1) / T;
    const int vecBlocks  = (N_NODES * (D_FEAT / 4) + T - 1) / T;   // 12500
    const int scatBlocks = (N_EDGES * 32 + T - 1) / T;             // 75000

    k_init_probe  <<<nodeBlocks, T>>>(ei);
    k_probe       <<<edgeBlocks, T>>>(ei);
    k_decode_count<<<edgeBlocks, T>>>(ei);
    k_dinv        <<<nodeBlocks, T>>>();
    k_scale_init  <<<vecBlocks,  T>>>((const float4*)x);
    k_scatter     <<<scatBlocks, T>>>();
    k_rescale     <<<vecBlocks,  T>>>();
    k_scatter     <<<scatBlocks, T>>>();
    k_classify    <<<1184, T>>>(W, b, out);
}

// round 7
// speedup vs baseline: 1.3560x; 1.3560x over previous
#include <cuda_runtime.h>

#define N_NODES   100000
#define N_EDGES   600000
#define D_FEAT    128
#define N_CLASSES 40
#define NB_SCAN   391        // ceil(N_NODES / 256)

// Scratch (allocation-free rule: __device__ globals).
// Kept under the R4-passing static footprint: 2*51.2MB bufs + ~4.0MB aux.
__device__ float g_bufA[(size_t)N_NODES * D_FEAT];
__device__ float g_bufB[(size_t)N_NODES * D_FEAT];
__device__ int   g_deg[N_NODES];
__device__ float g_dinv[N_NODES];
__device__ int   g_rowstart[N_NODES];
__device__ int   g_cursor[N_NODES];
__device__ int   g_csr[N_EDGES];        // src ids grouped by dst
__device__ int   g_blocksum[NB_SCAN];
__device__ int   g_blockoff[NB_SCAN];
__device__ unsigned g_fmt;              // 0 -> edge_index int64, else int32

// ---- init: zero deg, reset dtype probe ------------------------------------
__global__ void k_init() {
    int i = blockIdx.x * blockDim.x + threadIdx.x;
    if (i == 0) g_fmt = 0u;
    if (i < N_NODES) g_deg[i] = 0;
}

// dtype probe: OR all odd int32 words. int64 node ids (<1e5) have zero high
// halves -> OR==0; int32 layout puts random ids there -> OR!=0.
__global__ void k_probe(const int* __restrict__ e32) {
    int i = blockIdx.x * blockDim.x + threadIdx.x;
    unsigned v = 0;
    if (i < N_EDGES) v = (unsigned)e32[2 * i + 1];
    #pragma unroll
    for (int off = 16; off; off >>= 1)
        v |= __shfl_xor_sync(0xffffffffu, v, off);
    if ((threadIdx.x & 31) == 0 && v) atomicOr(&g_fmt, v);
}

__device__ __forceinline__ void decode_edge(const int* __restrict__ e32,
                                            int e, int& s, int& d) {
    if (g_fmt) { s = e32[e];     d = e32[N_EDGES + e]; }
    else       { s = e32[2 * e]; d = e32[2 * (N_EDGES + e)]; }
    if ((unsigned)s >= N_NODES) s = 0;   // defensive: soft-fail, no trap
    if ((unsigned)d >= N_NODES) d = 0;
}

// count in-degree (decode on the fly; no persisted src/dst arrays)
__global__ void k_count(const int* __restrict__ e32) {
    int e = blockIdx.x * blockDim.x + threadIdx.x;
    if (e >= N_EDGES) return;
    int s, d;
    decode_edge(e32, e, s, d);
    atomicAdd(&g_deg[d], 1);
}

__global__ void k_dinv() {
    int i = blockIdx.x * blockDim.x + threadIdx.x;
    if (i < N_NODES) g_dinv[i] = rsqrtf((float)g_deg[i] + 1.0f);
}

// ---- exclusive prefix sum of deg -> rowstart (3 kernels) ------------------
__global__ void k_block_scan() {
    int tid = threadIdx.x, lane = tid & 31, warp = tid >> 5;
    int i = blockIdx.x * 256 + tid;
    int v = (i < N_NODES) ? g_deg[i] : 0;
    int x = v;
    #pragma unroll
    for (int off = 1; off < 32; off <<= 1) {
        int y = __shfl_up_sync(0xffffffffu, x, off);
        if (lane >= off) x += y;
    }
    __shared__ int wsum[8];
    if (lane == 31) wsum[warp] = x;
    __syncthreads();
    if (tid < 8) {
        int wv = wsum[tid];
        #pragma unroll
        for (int off = 1; off < 8; off <<= 1) {
            int y = __shfl_up_sync(0xffu, wv, off);
            if (tid >= off) wv += y;
        }
        wsum[tid] = wv;                 // inclusive warp sums
    }
    __syncthreads();
    int base = (warp > 0) ? wsum[warp - 1] : 0;
    int incl = x + base;
    if (i < N_NODES) g_rowstart[i] = incl - v;   // block-local exclusive
    if (tid == 255) g_blocksum[blockIdx.x] = incl;
}

__global__ void k_scan_sums() {       // 1 block, 512 threads; NB_SCAN=391<512
    int tid = threadIdx.x, lane = tid & 31, warp = tid >> 5;
    int v = (tid < NB_SCAN) ? g_blocksum[tid] : 0;
    int x = v;
    #pragma unroll
    for (int off = 1; off < 32; off <<= 1) {
        int y = __shfl_up_sync(0xffffffffu, x, off);
        if (lane >= off) x += y;
    }
    __shared__ int wsum[16];
    if (lane == 31) wsum[warp] = x;
    __syncthreads();
    if (tid < 16) {
        int wv = wsum[tid];
        #pragma unroll
        for (int off = 1; off < 16; off <<= 1) {
            int y = __shfl_up_sync(0xffffu, wv, off);
            if (tid >= off) wv += y;
        }
        wsum[tid] = wv;
    }
    __syncthreads();
    int base = (warp > 0) ? wsum[warp - 1] : 0;
    if (tid < NB_SCAN) g_blockoff[tid] = x + base - v;   // exclusive
}

__global__ void k_finalize() {
    int i = blockIdx.x * blockDim.x + threadIdx.x;
    if (i >= N_NODES) return;
    int rs = g_rowstart[i] + g_blockoff[i >> 8];
    g_rowstart[i] = rs;
    g_cursor[i]   = rs;
}

// ---- bin edges into CSR (re-decode; int atomics on 100k cursors) ----------
__global__ void k_bin(const int* __restrict__ e32) {
    int e = blockIdx.x * blockDim.x + threadIdx.x;
    if (e >= N_EDGES) return;
    int s, d;
    decode_edge(e32, e, s, d);
    int pos = atomicAdd(&g_cursor[d], 1);
    g_csr[pos] = s;
}

// ---- u1 = dinv * x --------------------------------------------------------
__global__ void k_scale_init(const float4* __restrict__ x) {
    int t = blockIdx.x * blockDim.x + threadIdx.x;
    if (t >= N_NODES * (D_FEAT / 4)) return;
    int node = t >> 5;
    float d = g_dinv[node];
    float4 v = x[t];
    v.x *= d; v.y *= d; v.z *= d; v.w *= d;
    ((float4*)g_bufA)[t] = v;
}

// ---- pull-aggregation: one warp per node, no atomics ----------------------
// dst[node] = scale * ( src[node] + sum_{s in in(node)} src[s] )
// scale = dinv^2 (round 1, output feeds round 2) or dinv (final round).
// Buffers selected by template params INSIDE device code (no host-side
// device-symbol addresses — that is UB and tripped the allocation guard).
template<bool A2B, bool LAST>
__global__ void k_agg() {
    const float4* __restrict__ src =
        A2B ? (const float4*)g_bufA : (const float4*)g_bufB;
    float4* __restrict__ dst =
        A2B ? (float4*)g_bufB : (float4*)g_bufA;

    int w    = (blockIdx.x * blockDim.x + threadIdx.x) >> 5;
    int lane = threadIdx.x & 31;
    if (w >= N_NODES) return;
    int r0 = g_rowstart[w];
    int r1 = r0 + g_deg[w];
    float4 acc = src[w * 32 + lane];          // self-loop term (u[node])
    int e = r0;
    for (; e + 1 < r1; e += 2) {              // 2 gathers in flight
        int s0 = g_csr[e], s1 = g_csr[e + 1];
        float4 a = src[s0 * 32 + lane];
        float4 b = src[s1 * 32 + lane];
        acc.x += a.x + b.x; acc.y += a.y + b.y;
        acc.z += a.z + b.z; acc.w += a.w + b.w;
    }
    if (e < r1) {
        float4 a = src[g_csr[e] * 32 + lane];
        acc.x += a.x; acc.y += a.y; acc.z += a.z; acc.w += a.w;
    }
    float dv = g_dinv[w];
    float sc = LAST ? dv : dv * dv;
    acc.x *= sc; acc.y *= sc; acc.z *= sc; acc.w *= sc;
    dst[w * 32 + lane] = acc;
}

// ---- classifier: logits = bufA @ W^T + b ; log_softmax --------------------
__global__ void k_classify(const float* __restrict__ W,
                           const float* __restrict__ b,
                           float* __restrict__ out) {
    __shared__ float2 Wp[D_FEAT * 32];
    __shared__ float  bsh[64];
    __shared__ float  xsh[8][D_FEAT];

    for (int idx = threadIdx.x; idx < D_FEAT * 32; idx += blockDim.x) {
        int k = idx >> 5, c = idx & 31;
        float w0 = W[c * D_FEAT + k];
        float w1 = (c + 32 < N_CLASSES) ? W[(c + 32) * D_FEAT + k] : 0.0f;
        Wp[idx] = make_float2(w0, w1);
    }
    if (threadIdx.x < 64)
        bsh[threadIdx.x] = (threadIdx.x < N_CLASSES) ? b[threadIdx.x] : 0.0f;
    __syncthreads();

    int lane   = threadIdx.x & 31;
    int wlocal = threadIdx.x >> 5;
    int gwarp  = blockIdx.x * (blockDim.x >> 5) + wlocal;
    int nwarps = gridDim.x * (blockDim.x >> 5);

    for (int node = gwarp; node < N_NODES; node += nwarps) {
        float4 xv = ((const float4*)g_bufA)[node * 32 + lane];
        ((float4*)xsh[wlocal])[lane] = xv;
        __syncwarp();

        float acc0 = bsh[lane];
        float acc1 = bsh[lane + 32];
        #pragma unroll 8
        for (int k = 0; k < D_FEAT; k++) {
            float xk = xsh[wlocal][k];
            float2 wp = Wp[(k << 5) | lane];
            acc0 = fmaf(xk, wp.x, acc0);
            acc1 = fmaf(xk, wp.y, acc1);
        }

        float v1 = (lane < 8) ? acc1 : -1e30f;
        float m = fmaxf(acc0, v1);
        #pragma unroll
        for (int off = 16; off; off >>= 1)
            m = fmaxf(m, __shfl_xor_sync(0xffffffffu, m, off));
        float s = expf(acc0 - m) + ((lane < 8) ? expf(acc1 - m) : 0.0f);
        #pragma unroll
        for (int off = 16; off; off >>= 1)
            s += __shfl_xor_sync(0xffffffffu, s, off);
        float ls = m + logf(s);

        out[node * N_CLASSES + lane] = acc0 - ls;
        if (lane < 8)
            out[node * N_CLASSES + 32 + lane] = acc1 - ls;
        __syncwarp();
    }
}

extern "C" void kernel_launch(void* const* d_in, const int* in_sizes, int n_in,
                              void* d_out, int out_size) {
    const float* x  = (const float*)d_in[0];
    const int*   ei = (const int*)d_in[1];   // dtype resolved on device (g_fmt)
    const float* W  = (const float*)d_in[2];
    const float* b  = (const float*)d_in[3];
    float* out = (float*)d_out;

    const int T = 256;
    const int nodeBlocks = (N_NODES + T - 1) / T;                 // 391
    const int edgeBlocks = (N_EDGES + T - 1) / T;                 // 2344
    const int vecBlocks  = (N_NODES * (D_FEAT / 4) + T - 1) / T;  // 12500
    const int aggBlocks  = (N_NODES * 32 + T - 1) / T;            // 12500

    k_init       <<<nodeBlocks, T>>>();
    k_probe      <<<edgeBlocks, T>>>(ei);
    k_count      <<<edgeBlocks, T>>>(ei);
    k_dinv       <<<nodeBlocks, T>>>();
    k_block_scan <<<NB_SCAN,    T>>>();
    k_scan_sums  <<<1,        512>>>();
    k_finalize   <<<nodeBlocks, T>>>();
    k_bin        <<<edgeBlocks, T>>>(ei);
    k_scale_init <<<vecBlocks,  T>>>((const float4*)x);
    k_agg<true,  false><<<aggBlocks, T>>>();   // bufA -> bufB, scale dinv^2
    k_agg<false, true ><<<aggBlocks, T>>>();   // bufB -> bufA, scale dinv
    k_classify   <<<1184,       T>>>(W, b, out);
}